// round 16
// baseline (speedup 1.0000x reference)
#include <cuda_runtime.h>
#include <math.h>
#include <stdint.h>

#define N_TOK 4096
#define EMB   768
#define AED   512
#define NH    8
#define HD    64
#define KCL   32
#define THRS  1e-4f
#define EPSK  1e-6f
#define MAX_IT 100

typedef unsigned long long u64;

// ---------- packed f32x2 helpers (sm_103a FFMA2) ----------
__device__ __forceinline__ u64 pk2(float x, float y) {
    u64 r;
    asm("mov.b64 %0, {%1, %2};" : "=l"(r)
        : "r"(__float_as_uint(x)), "r"(__float_as_uint(y)));
    return r;
}
__device__ __forceinline__ float2 upk2(u64 v) {
    unsigned int lo, hi;
    asm("mov.b64 {%0, %1}, %2;" : "=r"(lo), "=r"(hi) : "l"(v));
    return make_float2(__uint_as_float(lo), __uint_as_float(hi));
}
__device__ __forceinline__ u64 fma2(u64 a, u64 b, u64 c) {
    u64 d;
    asm("fma.rn.f32x2 %0, %1, %2, %3;" : "=l"(d) : "l"(a), "l"(b), "l"(c));
    return d;
}
__device__ __forceinline__ u64 mul2(u64 a, u64 b) {
    u64 d;
    asm("mul.rn.f32x2 %0, %1, %2;" : "=l"(d) : "l"(a), "l"(b));
    return d;
}

// ---------------- device scratch ----------------
__device__ float g_WqF[EMB*AED];
__device__ float g_WkF[EMB*AED];
__device__ float g_WvF[EMB*AED];
__device__ float g_QH[N_TOK*AED];
__device__ float g_KH[N_TOK*AED];
__device__ float g_VH[N_TOK*AED];
__device__ float g_AO[N_TOK*AED];
__device__ float g_TR[N_TOK*AED];
__device__ float g_C[KCL*AED];
__device__ float g_Cnew[KCL*AED];
__device__ float g_Cacc[KCL*AED];
__device__ float g_asum[KCL];
__device__ float g_xn[N_TOK];
__device__ float g_diff;

// grid-barrier state (zero-initialized)
__device__ volatile unsigned g_bar_arrive;
__device__ volatile unsigned g_bar_gen;

// ====== SGEMM 64x64, BK=16, 4x4 micro, double-buffered + FFMA2 (verified) ==
template<bool TB, bool BIAS>
__global__ void __launch_bounds__(256)
gemm64(const float* __restrict__ A, const float* __restrict__ B,
       const float* __restrict__ bias, float* __restrict__ C,
       int M, int N, int K) {
    __shared__ float As[2][16][65];
    __shared__ float Bs[2][16][68];
    const int tid = threadIdx.x;
    const int tx = tid & 15, ty = tid >> 4;
    const int m0 = blockIdx.y * 64, n0 = blockIdx.x * 64;

    const int lm   = tid >> 2;
    const int lkq  = (tid & 3) * 4;
    const int lbn4 = (tid & 15) * 4;
    const int lbkk = tid >> 4;

    u64 acc2[4][2];
    #pragma unroll
    for (int i = 0; i < 4; i++) { acc2[i][0] = 0ull; acc2[i][1] = 0ull; }

    {
        float4 va = *(const float4*)(A + (size_t)(m0 + lm) * K + lkq);
        As[0][lkq+0][lm] = va.x; As[0][lkq+1][lm] = va.y;
        As[0][lkq+2][lm] = va.z; As[0][lkq+3][lm] = va.w;
        if (TB) {
            float4 vb = *(const float4*)(B + (size_t)(n0 + lm) * K + lkq);
            Bs[0][lkq+0][lm] = vb.x; Bs[0][lkq+1][lm] = vb.y;
            Bs[0][lkq+2][lm] = vb.z; Bs[0][lkq+3][lm] = vb.w;
        } else {
            float4 vb = *(const float4*)(B + (size_t)lbkk * N + n0 + lbn4);
            *(float4*)&Bs[0][lbkk][lbn4] = vb;
        }
    }
    __syncthreads();

    const int T = K / 16;
    int buf = 0;
    for (int t = 0; t < T; t++) {
        float4 pa, pb;
        const bool more = (t + 1 < T);
        if (more) {
            int k0 = (t + 1) * 16;
            pa = *(const float4*)(A + (size_t)(m0 + lm) * K + k0 + lkq);
            if (TB) pb = *(const float4*)(B + (size_t)(n0 + lm) * K + k0 + lkq);
            else    pb = *(const float4*)(B + (size_t)(k0 + lbkk) * N + n0 + lbn4);
        }
        const float (*Ab)[65] = As[buf];
        const float (*Bb)[68] = Bs[buf];
        #pragma unroll
        for (int k = 0; k < 16; k++) {
            float a0 = Ab[k][ty*4+0], a1 = Ab[k][ty*4+1];
            float a2 = Ab[k][ty*4+2], a3 = Ab[k][ty*4+3];
            ulonglong2 b2 = *(const ulonglong2*)&Bb[k][tx*4];
            u64 t0;
            t0 = pk2(a0, a0);
            acc2[0][0] = fma2(t0, b2.x, acc2[0][0]);
            acc2[0][1] = fma2(t0, b2.y, acc2[0][1]);
            t0 = pk2(a1, a1);
            acc2[1][0] = fma2(t0, b2.x, acc2[1][0]);
            acc2[1][1] = fma2(t0, b2.y, acc2[1][1]);
            t0 = pk2(a2, a2);
            acc2[2][0] = fma2(t0, b2.x, acc2[2][0]);
            acc2[2][1] = fma2(t0, b2.y, acc2[2][1]);
            t0 = pk2(a3, a3);
            acc2[3][0] = fma2(t0, b2.x, acc2[3][0]);
            acc2[3][1] = fma2(t0, b2.y, acc2[3][1]);
        }
        if (more) {
            int nb = buf ^ 1;
            As[nb][lkq+0][lm] = pa.x; As[nb][lkq+1][lm] = pa.y;
            As[nb][lkq+2][lm] = pa.z; As[nb][lkq+3][lm] = pa.w;
            if (TB) {
                Bs[nb][lkq+0][lm] = pb.x; Bs[nb][lkq+1][lm] = pb.y;
                Bs[nb][lkq+2][lm] = pb.z; Bs[nb][lkq+3][lm] = pb.w;
            } else {
                *(float4*)&Bs[nb][lbkk][lbn4] = pb;
            }
            __syncthreads();
            buf = nb;
        }
    }
    #pragma unroll
    for (int i = 0; i < 4; i++) {
        float2 lo = upk2(acc2[i][0]);
        float2 hi = upk2(acc2[i][1]);
        float c0 = lo.x, c1 = lo.y, c2 = hi.x, c3 = hi.y;
        if (BIAS) {
            c0 += bias[n0 + tx*4 + 0]; c1 += bias[n0 + tx*4 + 1];
            c2 += bias[n0 + tx*4 + 2]; c3 += bias[n0 + tx*4 + 3];
        }
        *(float4*)(C + (size_t)(m0 + ty*4 + i) * N + n0 + tx*4) =
            make_float4(c0, c1, c2, c3);
    }
}

// ====== flash attention BM=BN=64 + FFMA2 (7579us-verified, untouched) ======
#define AST 68
#define ATTN_SMEM_FLOATS (4 * 64 * AST)
__global__ void __launch_bounds__(256)
attn_kernel(const float* __restrict__ Q, const float* __restrict__ K,
            const float* __restrict__ V, float* __restrict__ O) {
    extern __shared__ float sm[];
    float* Qst = sm;
    float* Kst = Qst + 64 * AST;
    float* Vs  = Kst + 64 * AST;
    float* Ss  = Vs  + 64 * AST;

    const int h = blockIdx.y;
    const int m0 = blockIdx.x * 64;
    const int tid = threadIdx.x;
    const int tx = tid & 15, ty = tid >> 4;

    #pragma unroll
    for (int it = 0; it < 4; it++) {
        int idx = tid + it * 256;
        int r = idx >> 4, c4 = idx & 15;
        float4 v = *(const float4*)(Q + (size_t)(m0 + r) * AED + h * HD + c4 * 4);
        Qst[(c4*4+0)*AST + r] = v.x;
        Qst[(c4*4+1)*AST + r] = v.y;
        Qst[(c4*4+2)*AST + r] = v.z;
        Qst[(c4*4+3)*AST + r] = v.w;
    }

    u64 acc2[4][2];
    #pragma unroll
    for (int i = 0; i < 4; i++) { acc2[i][0] = 0ull; acc2[i][1] = 0ull; }
    float m_run[4], l_run[4];
    #pragma unroll
    for (int i = 0; i < 4; i++) { m_run[i] = -INFINITY; l_run[i] = 0.f; }

    for (int kb = 0; kb < N_TOK; kb += 64) {
        __syncthreads();
        #pragma unroll
        for (int it = 0; it < 4; it++) {
            int idx = tid + it * 256;
            int r = idx >> 4, c4 = idx & 15;
            float4 v = *(const float4*)(K + (size_t)(kb + r) * AED + h * HD + c4 * 4);
            Kst[(c4*4+0)*AST + r] = v.x;
            Kst[(c4*4+1)*AST + r] = v.y;
            Kst[(c4*4+2)*AST + r] = v.z;
            Kst[(c4*4+3)*AST + r] = v.w;
            float4 w = *(const float4*)(V + (size_t)(kb + r) * AED + h * HD + c4 * 4);
            *(float4*)&Vs[r * AST + c4 * 4] = w;
        }
        __syncthreads();

        u64 s2[4][2];
        #pragma unroll
        for (int i = 0; i < 4; i++) { s2[i][0] = 0ull; s2[i][1] = 0ull; }
        #pragma unroll 4
        for (int k = 0; k < 64; k++) {
            float4 a4 = *(const float4*)&Qst[k * AST + ty * 4];
            ulonglong2 b2 = *(const ulonglong2*)&Kst[k * AST + tx * 4];
            u64 t0;
            t0 = pk2(a4.x, a4.x);
            s2[0][0] = fma2(t0, b2.x, s2[0][0]);
            s2[0][1] = fma2(t0, b2.y, s2[0][1]);
            t0 = pk2(a4.y, a4.y);
            s2[1][0] = fma2(t0, b2.x, s2[1][0]);
            s2[1][1] = fma2(t0, b2.y, s2[1][1]);
            t0 = pk2(a4.z, a4.z);
            s2[2][0] = fma2(t0, b2.x, s2[2][0]);
            s2[2][1] = fma2(t0, b2.y, s2[2][1]);
            t0 = pk2(a4.w, a4.w);
            s2[3][0] = fma2(t0, b2.x, s2[3][0]);
            s2[3][1] = fma2(t0, b2.y, s2[3][1]);
        }
        float s[4][4];
        #pragma unroll
        for (int i = 0; i < 4; i++) {
            float2 lo = upk2(s2[i][0]);
            float2 hi = upk2(s2[i][1]);
            s[i][0] = lo.x; s[i][1] = lo.y; s[i][2] = hi.x; s[i][3] = hi.y;
        }

        float alpha[4];
        #pragma unroll
        for (int i = 0; i < 4; i++) {
            float mx = s[i][0] * 0.125f;
            #pragma unroll
            for (int j = 0; j < 4; j++) { s[i][j] *= 0.125f; mx = fmaxf(mx, s[i][j]); }
            #pragma unroll
            for (int off = 8; off >= 1; off >>= 1)
                mx = fmaxf(mx, __shfl_xor_sync(0xffffffffu, mx, off));
            float mnew = fmaxf(m_run[i], mx);
            alpha[i] = __expf(m_run[i] - mnew);
            float ps = 0.f;
            #pragma unroll
            for (int j = 0; j < 4; j++) {
                s[i][j] = __expf(s[i][j] - mnew);
                ps += s[i][j];
            }
            #pragma unroll
            for (int off = 8; off >= 1; off >>= 1)
                ps += __shfl_xor_sync(0xffffffffu, ps, off);
            l_run[i] = l_run[i] * alpha[i] + ps;
            m_run[i] = mnew;
        }
        #pragma unroll
        for (int i = 0; i < 4; i++) {
            *(float4*)&Ss[(ty * 4 + i) * AST + tx * 4] =
                make_float4(s[i][0], s[i][1], s[i][2], s[i][3]);
            u64 aa = pk2(alpha[i], alpha[i]);
            acc2[i][0] = mul2(acc2[i][0], aa);
            acc2[i][1] = mul2(acc2[i][1], aa);
        }
        __syncthreads();

        #pragma unroll 4
        for (int nq = 0; nq < 16; nq++) {
            float4 p[4];
            #pragma unroll
            for (int i = 0; i < 4; i++)
                p[i] = *(const float4*)&Ss[(ty * 4 + i) * AST + nq * 4];
            #pragma unroll
            for (int u = 0; u < 4; u++) {
                ulonglong2 v2 = *(const ulonglong2*)&Vs[(nq * 4 + u) * AST + tx * 4];
                float pv[4] = {p[0].x, p[1].x, p[2].x, p[3].x};
                if (u == 1) { pv[0]=p[0].y; pv[1]=p[1].y; pv[2]=p[2].y; pv[3]=p[3].y; }
                if (u == 2) { pv[0]=p[0].z; pv[1]=p[1].z; pv[2]=p[2].z; pv[3]=p[3].z; }
                if (u == 3) { pv[0]=p[0].w; pv[1]=p[1].w; pv[2]=p[2].w; pv[3]=p[3].w; }
                #pragma unroll
                for (int i = 0; i < 4; i++) {
                    u64 pu = pk2(pv[i], pv[i]);
                    acc2[i][0] = fma2(pu, v2.x, acc2[i][0]);
                    acc2[i][1] = fma2(pu, v2.y, acc2[i][1]);
                }
            }
        }
    }

    #pragma unroll
    for (int i = 0; i < 4; i++) {
        float inv = 1.f / l_run[i];
        float2 lo = upk2(acc2[i][0]);
        float2 hi = upk2(acc2[i][1]);
        *(float4*)(O + (size_t)(m0 + ty * 4 + i) * AED + h * HD + tx * 4) =
            make_float4(lo.x*inv, lo.y*inv, hi.x*inv, hi.y*inv);
    }
}

// ================= persistent DKM (7579us-verified, untouched) =================
#define NB_DKM 128
#define XST  516
#define XST4 129
#define AS_ST 36
#define DKM_SMEM_FLOATS (2 * KCL * XST + KCL * AS_ST + 64)

__device__ __forceinline__ void grid_bar() {
    __syncthreads();
    if (threadIdx.x == 0) {
        __threadfence();
        unsigned gen = g_bar_gen;
        if (atomicAdd((unsigned*)&g_bar_arrive, 1u) == NB_DKM - 1) {
            g_bar_arrive = 0;
            __threadfence();
            g_bar_gen = gen + 1;
        } else {
            while (g_bar_gen == gen) { }
        }
        __threadfence();
    }
    __syncthreads();
}

__global__ void __launch_bounds__(256)
dkm_persist(const float* __restrict__ X, const int* __restrict__ idx,
            float* __restrict__ a_out) {
    extern __shared__ float sm[];
    float* Xs     = sm;
    float* Cs     = Xs + KCL * XST;
    float* a_s    = Cs + KCL * XST;
    float* asum_s = a_s + KCL * AS_ST;
    float* cn_s   = asum_s + KCL;
    __shared__ float redw[8];

    const int tid = threadIdx.x;
    const int b = blockIdx.x;
    const int tx = tid & 15, ty = tid >> 4;
    const int rbase = b * 32;
    const int w = tid >> 5, lane = tid & 31;

    for (int itr = 0; itr < 4; itr++) {
        int row = rbase + w * 4 + itr;
        const float4* xr = (const float4*)(X + (size_t)row * AED);
        float p = 0.f;
        #pragma unroll
        for (int i = 0; i < 4; i++) {
            float4 v = xr[i * 32 + lane];
            p += v.x*v.x + v.y*v.y + v.z*v.z + v.w*v.w;
        }
        #pragma unroll
        for (int off = 16; off >= 1; off >>= 1)
            p += __shfl_xor_sync(0xffffffffu, p, off);
        if (lane == 0) g_xn[row] = p;
    }
    for (int i = tid; i < KCL * 128; i += 256) {
        int r = i >> 7, c4 = i & 127;
        ((float4*)Xs)[r * XST4 + c4] =
            ((const float4*)X)[(size_t)(rbase + r) * 128 + c4];
    }
    if (tid < 128) g_Cacc[b * 128 + tid] = 0.f;
    if (b == 0) {
        for (int i = tid; i < KCL * AED; i += 256) {
            int r = i >> 9, c = i & 511;
            g_C[i] = X[(size_t)idx[r] * AED + c];
        }
        if (tid < KCL) g_asum[tid] = 0.f;
    }
    grid_bar();

    for (int it = 0; ; it++) {
        for (int i = tid; i < KCL * 128; i += 256) {
            int r = i >> 7, c4 = i & 127;
            ((float4*)Cs)[r * XST4 + c4] = ((const float4*)g_C)[r * 128 + c4];
        }
        if (tid < KCL) asum_s[tid] = 0.f;
        if (b == 0 && tid == 0) g_diff = 0.f;
        __syncthreads();
        {
            int j = tid >> 3, s7 = tid & 7;
            float p = 0.f;
            const float4* cr = (const float4*)(Cs + (size_t)j * XST);
            #pragma unroll
            for (int i = 0; i < 16; i++) {
                float4 v = cr[s7 * 16 + i];
                p += v.x*v.x + v.y*v.y + v.z*v.z + v.w*v.w;
            }
            p += __shfl_xor_sync(0xffffffffu, p, 4);
            p += __shfl_xor_sync(0xffffffffu, p, 2);
            p += __shfl_xor_sync(0xffffffffu, p, 1);
            if (s7 == 0) cn_s[j] = p;
        }
        __syncthreads();

        const ulonglong2* X0 = (const ulonglong2*)(Xs + (size_t)(ty * 2 + 0) * XST);
        const ulonglong2* X1 = (const ulonglong2*)(Xs + (size_t)(ty * 2 + 1) * XST);
        const ulonglong2* C0 = (const ulonglong2*)(Cs + (size_t)(tx * 2 + 0) * XST);
        const ulonglong2* C1 = (const ulonglong2*)(Cs + (size_t)(tx * 2 + 1) * XST);
        u64 dd[2][2];
        dd[0][0] = dd[0][1] = dd[1][0] = dd[1][1] = 0ull;
        #pragma unroll 4
        for (int k4 = 0; k4 < 128; k4++) {
            ulonglong2 a0 = X0[k4];
            ulonglong2 a1 = X1[k4];
            ulonglong2 b0 = C0[k4];
            ulonglong2 b1 = C1[k4];
            dd[0][0] = fma2(a0.x, b0.x, dd[0][0]);
            dd[0][0] = fma2(a0.y, b0.y, dd[0][0]);
            dd[0][1] = fma2(a0.x, b1.x, dd[0][1]);
            dd[0][1] = fma2(a0.y, b1.y, dd[0][1]);
            dd[1][0] = fma2(a1.x, b0.x, dd[1][0]);
            dd[1][0] = fma2(a1.y, b0.y, dd[1][0]);
            dd[1][1] = fma2(a1.x, b1.x, dd[1][1]);
            dd[1][1] = fma2(a1.y, b1.y, dd[1][1]);
        }
        float dot[2][2];
        #pragma unroll
        for (int i = 0; i < 2; i++)
            #pragma unroll
            for (int j = 0; j < 2; j++) {
                float2 t = upk2(dd[i][j]);
                dot[i][j] = t.x + t.y;
            }

        float asum_part[2] = {0.f, 0.f};
        #pragma unroll
        for (int i = 0; i < 2; i++) {
            int row = rbase + ty * 2 + i;
            float xn = g_xn[row];
            float lg[2];
            #pragma unroll
            for (int j = 0; j < 2; j++) {
                float d2 = xn + cn_s[tx * 2 + j] - 2.f * dot[i][j];
                lg[j] = -2.f * sqrtf(fmaxf(d2, 0.f));
            }
            float mx = fmaxf(lg[0], lg[1]);
            #pragma unroll
            for (int off = 8; off >= 1; off >>= 1)
                mx = fmaxf(mx, __shfl_xor_sync(0xffffffffu, mx, off));
            float e0 = __expf(lg[0] - mx), e1 = __expf(lg[1] - mx);
            float ss = e0 + e1;
            #pragma unroll
            for (int off = 8; off >= 1; off >>= 1)
                ss += __shfl_xor_sync(0xffffffffu, ss, off);
            float inv = 1.f / ss;
            float a0v = e0 * inv, a1v = e1 * inv;
            a_out[(size_t)row * KCL + tx * 2 + 0] = a0v;
            a_out[(size_t)row * KCL + tx * 2 + 1] = a1v;
            a_s[(ty * 2 + i) * AS_ST + tx * 2 + 0] = a0v;
            a_s[(ty * 2 + i) * AS_ST + tx * 2 + 1] = a1v;
            asum_part[0] += a0v; asum_part[1] += a1v;
        }
        atomicAdd(&asum_s[tx * 2 + 0], asum_part[0]);
        atomicAdd(&asum_s[tx * 2 + 1], asum_part[1]);
        __syncthreads();
        if (tid < KCL) atomicAdd(&g_asum[tid], asum_s[tid]);

        {
            const int k4 = tid & 127;
            const int jg = tid >> 7;
            u64 av2[16][2];
            #pragma unroll
            for (int jj = 0; jj < 16; jj++) { av2[jj][0] = 0ull; av2[jj][1] = 0ull; }
            for (int r = 0; r < 32; r++) {
                ulonglong2 x2 = *(const ulonglong2*)(Xs + (size_t)r * XST + k4 * 4);
                #pragma unroll
                for (int q = 0; q < 4; q++) {
                    float4 av = ((const float4*)a_s)[r * 9 + jg * 4 + q];
                    float a[4] = {av.x, av.y, av.z, av.w};
                    #pragma unroll
                    for (int u = 0; u < 4; u++) {
                        int jj = q * 4 + u;
                        u64 pu = pk2(a[u], a[u]);
                        av2[jj][0] = fma2(pu, x2.x, av2[jj][0]);
                        av2[jj][1] = fma2(pu, x2.y, av2[jj][1]);
                    }
                }
            }
            #pragma unroll
            for (int jj = 0; jj < 16; jj++) {
                float* dst = g_Cacc + (size_t)(jg * 16 + jj) * AED + k4 * 4;
                float2 lo = upk2(av2[jj][0]);
                float2 hi = upk2(av2[jj][1]);
                atomicAdd(dst + 0, lo.x);
                atomicAdd(dst + 1, lo.y);
                atomicAdd(dst + 2, hi.x);
                atomicAdd(dst + 3, hi.y);
            }
        }
        grid_bar();

        float dsum = 0.f;
        if (tid < 128) {
            int i = b * 128 + tid;
            int j = i >> 9;
            float cn_ = g_Cacc[i] / (g_asum[j] + EPSK);
            g_Cnew[i] = cn_;
            dsum = fabsf(cn_ - g_C[i]);
        }
        #pragma unroll
        for (int off = 16; off >= 1; off >>= 1)
            dsum += __shfl_xor_sync(0xffffffffu, dsum, off);
        if (lane == 0) redw[w] = dsum;
        __syncthreads();
        if (tid == 0) {
            float t = redw[0] + redw[1] + redw[2] + redw[3]
                    + redw[4] + redw[5] + redw[6] + redw[7];
            atomicAdd(&g_diff, t);
        }
        grid_bar();

        float diff = *((volatile float*)&g_diff);
        if (it == MAX_IT || !(diff > THRS)) break;
        if (tid < 128) {
            int i = b * 128 + tid;
            g_C[i] = g_Cnew[i];
            g_Cacc[i] = 0.f;
        }
        if (b == 0 && tid < KCL) g_asum[tid] = 0.f;
        grid_bar();
    }
}

__global__ void copy_out(float* __restrict__ out) {
    int i = blockIdx.x * 256 + threadIdx.x;
    out[i] = g_C[i];
}

// ================= launch =================
extern "C" void kernel_launch(void* const* d_in, const int* in_sizes, int n_in,
                              void* d_out, int out_size) {
    const float* X   = (const float*)d_in[0];
    const float* qw  = (const float*)d_in[1];
    const float* kw  = (const float*)d_in[2];
    const float* vw  = (const float*)d_in[3];
    const float* ipw = (const float*)d_in[4];
    const float* ipb = (const float*)d_in[5];
    const float* ow  = (const float*)d_in[6];
    const float* ob  = (const float*)d_in[7];
    const int*   idx = (const int*)d_in[8];

    float* out   = (float*)d_out;
    float* a_out = out + KCL * AED;

    cudaFuncSetAttribute(attn_kernel, cudaFuncAttributeMaxDynamicSharedMemorySize,
                         ATTN_SMEM_FLOATS * 4);
    cudaFuncSetAttribute(dkm_persist, cudaFuncAttributeMaxDynamicSharedMemorySize,
                         DKM_SMEM_FLOATS * 4);

    // fused projection weights: W*F = qw @ Wq^T etc.  [768,512]
    dim3 gW(AED/64, EMB/64);
    gemm64<true, false><<<gW, 256>>>(qw, ipw,               nullptr, g_WqF, EMB, AED, AED);
    gemm64<true, false><<<gW, 256>>>(kw, ipw + AED*AED,     nullptr, g_WkF, EMB, AED, AED);
    gemm64<true, false><<<gW, 256>>>(vw, ipw + 2*AED*AED,   nullptr, g_WvF, EMB, AED, AED);

    // projections [4096,512] = X @ WF + b
    dim3 gP(AED/64, N_TOK/64);
    gemm64<false, true><<<gP, 256>>>(X, g_WqF, ipb,          g_QH, N_TOK, AED, EMB);
    gemm64<false, true><<<gP, 256>>>(X, g_WkF, ipb + AED,    g_KH, N_TOK, AED, EMB);
    gemm64<false, true><<<gP, 256>>>(X, g_WvF, ipb + 2*AED,  g_VH, N_TOK, AED, EMB);

    // attention — launched TWICE (idempotent): total delta vs 7579us build = T_attn
    attn_kernel<<<dim3(N_TOK/64, NH), 256, ATTN_SMEM_FLOATS*4>>>(g_QH, g_KH, g_VH, g_AO);
    attn_kernel<<<dim3(N_TOK/64, NH), 256, ATTN_SMEM_FLOATS*4>>>(g_QH, g_KH, g_VH, g_AO);

    // output projection
    gemm64<true, true><<<gP, 256>>>(g_AO, ow, ob, g_TR, N_TOK, AED, AED);

    // persistent DKM (X tile smem-resident)
    dkm_persist<<<NB_DKM, 256, DKM_SMEM_FLOATS*4>>>(g_TR, idx, a_out);

    copy_out<<<KCL*AED/256, 256>>>(out);
}

// round 17
// speedup vs baseline: 1.8089x; 1.8089x over previous
#include <cuda_runtime.h>
#include <math.h>
#include <stdint.h>

#define N_TOK 4096
#define EMB   768
#define AED   512
#define NH    8
#define HD    64
#define KCL   32
#define THRS  1e-4f
#define EPSK  1e-6f
#define MAX_IT 100

typedef unsigned long long u64;

// ---------- packed f32x2 helpers (sm_103a FFMA2) ----------
__device__ __forceinline__ u64 pk2(float x, float y) {
    u64 r;
    asm("mov.b64 %0, {%1, %2};" : "=l"(r)
        : "r"(__float_as_uint(x)), "r"(__float_as_uint(y)));
    return r;
}
__device__ __forceinline__ float2 upk2(u64 v) {
    unsigned int lo, hi;
    asm("mov.b64 {%0, %1}, %2;" : "=r"(lo), "=r"(hi) : "l"(v));
    return make_float2(__uint_as_float(lo), __uint_as_float(hi));
}
__device__ __forceinline__ u64 fma2(u64 a, u64 b, u64 c) {
    u64 d;
    asm("fma.rn.f32x2 %0, %1, %2, %3;" : "=l"(d) : "l"(a), "l"(b), "l"(c));
    return d;
}

// ---------- tf32 mma helpers ----------
__device__ __forceinline__ uint32_t tf32r(float x) {
    uint32_t r;
    asm("cvt.rna.tf32.f32 %0, %1;" : "=r"(r) : "f"(x));
    return r;
}
__device__ __forceinline__ void tf32_split(float x, uint32_t& h, uint32_t& l) {
    h = tf32r(x);
    l = tf32r(x - __uint_as_float(h));
}
__device__ __forceinline__ void mma8(float* d, const uint32_t* a, const uint32_t* b) {
    asm volatile(
        "mma.sync.aligned.m16n8k8.row.col.f32.tf32.tf32.f32 "
        "{%0,%1,%2,%3},{%4,%5,%6,%7},{%8,%9},{%0,%1,%2,%3};"
        : "+f"(d[0]), "+f"(d[1]), "+f"(d[2]), "+f"(d[3])
        : "r"(a[0]), "r"(a[1]), "r"(a[2]), "r"(a[3]), "r"(b[0]), "r"(b[1]));
}

// ---------------- device scratch ----------------
__device__ float g_WqF[EMB*AED];
__device__ float g_WkF[EMB*AED];
__device__ float g_WvF[EMB*AED];
__device__ float g_QH[N_TOK*AED];
__device__ float g_KH[N_TOK*AED];
__device__ float g_VH[N_TOK*AED];
__device__ float g_AO[N_TOK*AED];
__device__ float g_TR[N_TOK*AED];
__device__ float g_C[KCL*AED];
__device__ float g_Cnew[KCL*AED];
__device__ float g_Cacc[KCL*AED];
__device__ float g_asum[KCL];
__device__ float g_xn[N_TOK];
__device__ float g_diff;

// grid-barrier state (zero-initialized)
__device__ volatile unsigned g_bar_arrive;
__device__ volatile unsigned g_bar_gen;

// ====== SGEMM 64x64, BK=16, 4x4 micro, double-buffered + FFMA2 (verified) ==
template<bool TB, bool BIAS>
__global__ void __launch_bounds__(256)
gemm64(const float* __restrict__ A, const float* __restrict__ B,
       const float* __restrict__ bias, float* __restrict__ C,
       int M, int N, int K) {
    __shared__ float As[2][16][65];
    __shared__ float Bs[2][16][68];
    const int tid = threadIdx.x;
    const int tx = tid & 15, ty = tid >> 4;
    const int m0 = blockIdx.y * 64, n0 = blockIdx.x * 64;

    const int lm   = tid >> 2;
    const int lkq  = (tid & 3) * 4;
    const int lbn4 = (tid & 15) * 4;
    const int lbkk = tid >> 4;

    u64 acc2[4][2];
    #pragma unroll
    for (int i = 0; i < 4; i++) { acc2[i][0] = 0ull; acc2[i][1] = 0ull; }

    {
        float4 va = *(const float4*)(A + (size_t)(m0 + lm) * K + lkq);
        As[0][lkq+0][lm] = va.x; As[0][lkq+1][lm] = va.y;
        As[0][lkq+2][lm] = va.z; As[0][lkq+3][lm] = va.w;
        if (TB) {
            float4 vb = *(const float4*)(B + (size_t)(n0 + lm) * K + lkq);
            Bs[0][lkq+0][lm] = vb.x; Bs[0][lkq+1][lm] = vb.y;
            Bs[0][lkq+2][lm] = vb.z; Bs[0][lkq+3][lm] = vb.w;
        } else {
            float4 vb = *(const float4*)(B + (size_t)lbkk * N + n0 + lbn4);
            *(float4*)&Bs[0][lbkk][lbn4] = vb;
        }
    }
    __syncthreads();

    const int T = K / 16;
    int buf = 0;
    for (int t = 0; t < T; t++) {
        float4 pa, pb;
        const bool more = (t + 1 < T);
        if (more) {
            int k0 = (t + 1) * 16;
            pa = *(const float4*)(A + (size_t)(m0 + lm) * K + k0 + lkq);
            if (TB) pb = *(const float4*)(B + (size_t)(n0 + lm) * K + k0 + lkq);
            else    pb = *(const float4*)(B + (size_t)(k0 + lbkk) * N + n0 + lbn4);
        }
        const float (*Ab)[65] = As[buf];
        const float (*Bb)[68] = Bs[buf];
        #pragma unroll
        for (int k = 0; k < 16; k++) {
            float a0 = Ab[k][ty*4+0], a1 = Ab[k][ty*4+1];
            float a2 = Ab[k][ty*4+2], a3 = Ab[k][ty*4+3];
            ulonglong2 b2 = *(const ulonglong2*)&Bb[k][tx*4];
            u64 t0;
            t0 = pk2(a0, a0);
            acc2[0][0] = fma2(t0, b2.x, acc2[0][0]);
            acc2[0][1] = fma2(t0, b2.y, acc2[0][1]);
            t0 = pk2(a1, a1);
            acc2[1][0] = fma2(t0, b2.x, acc2[1][0]);
            acc2[1][1] = fma2(t0, b2.y, acc2[1][1]);
            t0 = pk2(a2, a2);
            acc2[2][0] = fma2(t0, b2.x, acc2[2][0]);
            acc2[2][1] = fma2(t0, b2.y, acc2[2][1]);
            t0 = pk2(a3, a3);
            acc2[3][0] = fma2(t0, b2.x, acc2[3][0]);
            acc2[3][1] = fma2(t0, b2.y, acc2[3][1]);
        }
        if (more) {
            int nb = buf ^ 1;
            As[nb][lkq+0][lm] = pa.x; As[nb][lkq+1][lm] = pa.y;
            As[nb][lkq+2][lm] = pa.z; As[nb][lkq+3][lm] = pa.w;
            if (TB) {
                Bs[nb][lkq+0][lm] = pb.x; Bs[nb][lkq+1][lm] = pb.y;
                Bs[nb][lkq+2][lm] = pb.z; Bs[nb][lkq+3][lm] = pb.w;
            } else {
                *(float4*)&Bs[nb][lbkk][lbn4] = pb;
            }
            __syncthreads();
            buf = nb;
        }
    }
    #pragma unroll
    for (int i = 0; i < 4; i++) {
        float2 lo = upk2(acc2[i][0]);
        float2 hi = upk2(acc2[i][1]);
        float c0 = lo.x, c1 = lo.y, c2 = hi.x, c3 = hi.y;
        if (BIAS) {
            c0 += bias[n0 + tx*4 + 0]; c1 += bias[n0 + tx*4 + 1];
            c2 += bias[n0 + tx*4 + 2]; c3 += bias[n0 + tx*4 + 3];
        }
        *(float4*)(C + (size_t)(m0 + ty*4 + i) * N + n0 + tx*4) =
            make_float4(c0, c1, c2, c3);
    }
}

// ====== attention via mma.sync tf32 (3-term split => fp32 accuracy) ======
// CTA: 128 threads (4 warps). BM=64 (warp w: rows 16w..16w+15). BN=64 keys/tile.
#define KST 76     // smem row stride: 76 % 32 == 12 -> both frag patterns conflict-free
#define ATTN_SMEM_FLOATS (2 * 64 * KST + 4 * 16 * KST)
__global__ void __launch_bounds__(128)
attn_mma(const float* __restrict__ Q, const float* __restrict__ K,
         const float* __restrict__ V, float* __restrict__ O) {
    extern __shared__ float sm[];
    float* Ks = sm;                 // [64][KST]
    float* Vs = Ks + 64 * KST;      // [64][KST]
    float* Ps = Vs + 64 * KST;      // [4][16][KST] per-warp P staging

    const int h = blockIdx.y;
    const int m0 = blockIdx.x * 64;
    const int tid = threadIdx.x;
    const int w = tid >> 5, lane = tid & 31;
    const int g = lane >> 2, t = lane & 3;

    // ---- Q fragments (hi + lo), loaded once ----
    // a0:(g,t) a1:(g+8,t) a2:(g,t+4) a3:(g+8,t+4) within warp's m16 x k8 chunk c
    uint32_t qh[8][4], ql[8][4];
    {
        const float* Qr0 = Q + (size_t)(m0 + w * 16 + g) * AED + h * HD;
        const float* Qr1 = Qr0 + 8 * AED;
        #pragma unroll
        for (int c = 0; c < 8; c++) {
            tf32_split(Qr0[c * 8 + t],     qh[c][0], ql[c][0]);
            tf32_split(Qr1[c * 8 + t],     qh[c][1], ql[c][1]);
            tf32_split(Qr0[c * 8 + t + 4], qh[c][2], ql[c][2]);
            tf32_split(Qr1[c * 8 + t + 4], qh[c][3], ql[c][3]);
        }
    }

    float o[8][4];
    #pragma unroll
    for (int j = 0; j < 8; j++)
        o[j][0] = o[j][1] = o[j][2] = o[j][3] = 0.f;
    float mrow[2] = {-INFINITY, -INFINITY};
    float lrow[2] = {0.f, 0.f};

    for (int kb = 0; kb < N_TOK; kb += 64) {
        __syncthreads();   // prior tile's Ks/Vs reads done
        #pragma unroll
        for (int it = 0; it < 8; it++) {
            int idx = tid + it * 128;          // 1024 float4 per tile
            int r = idx >> 4, c4 = idx & 15;
            *(float4*)&Ks[r * KST + c4 * 4] =
                *(const float4*)(K + (size_t)(kb + r) * AED + h * HD + c4 * 4);
            *(float4*)&Vs[r * KST + c4 * 4] =
                *(const float4*)(V + (size_t)(kb + r) * AED + h * HD + c4 * 4);
        }
        __syncthreads();

        // ---- S = Q @ K^T ----
        float s[8][4];
        #pragma unroll
        for (int j = 0; j < 8; j++)
            s[j][0] = s[j][1] = s[j][2] = s[j][3] = 0.f;
        #pragma unroll
        for (int c = 0; c < 8; c++) {
            #pragma unroll
            for (int j = 0; j < 8; j++) {
                // B frag: b0 = K^T[k=c*8+t][n=j*8+g] = Ks[j*8+g][c*8+t]
                uint32_t bh[2], bl[2];
                tf32_split(Ks[(j * 8 + g) * KST + c * 8 + t],     bh[0], bl[0]);
                tf32_split(Ks[(j * 8 + g) * KST + c * 8 + t + 4], bh[1], bl[1]);
                mma8(s[j], qh[c], bh);
                mma8(s[j], ql[c], bh);
                mma8(s[j], qh[c], bl);
            }
        }

        // ---- online softmax on C-frags (rows g, g+8; quad shfl 1,2) ----
        float alpha[2];
        #pragma unroll
        for (int rr = 0; rr < 2; rr++) {
            float mx = -INFINITY;
            #pragma unroll
            for (int j = 0; j < 8; j++) {
                s[j][rr * 2 + 0] *= 0.125f;
                s[j][rr * 2 + 1] *= 0.125f;
                mx = fmaxf(mx, fmaxf(s[j][rr * 2 + 0], s[j][rr * 2 + 1]));
            }
            mx = fmaxf(mx, __shfl_xor_sync(0xffffffffu, mx, 1));
            mx = fmaxf(mx, __shfl_xor_sync(0xffffffffu, mx, 2));
            float mnew = fmaxf(mrow[rr], mx);
            alpha[rr] = __expf(mrow[rr] - mnew);
            float ps = 0.f;
            #pragma unroll
            for (int j = 0; j < 8; j++) {
                s[j][rr * 2 + 0] = __expf(s[j][rr * 2 + 0] - mnew);
                s[j][rr * 2 + 1] = __expf(s[j][rr * 2 + 1] - mnew);
                ps += s[j][rr * 2 + 0] + s[j][rr * 2 + 1];
            }
            ps += __shfl_xor_sync(0xffffffffu, ps, 1);
            ps += __shfl_xor_sync(0xffffffffu, ps, 2);
            lrow[rr] = lrow[rr] * alpha[rr] + ps;
            mrow[rr] = mnew;
            #pragma unroll
            for (int j = 0; j < 8; j++) {
                o[j][rr * 2 + 0] *= alpha[rr];
                o[j][rr * 2 + 1] *= alpha[rr];
            }
        }

        // ---- stage P in per-warp smem, re-fragment as mma-A ----
        float* Pw = Ps + w * 16 * KST;
        __syncwarp();
        #pragma unroll
        for (int j = 0; j < 8; j++) {
            *(float2*)&Pw[g * KST + j * 8 + t * 2] =
                make_float2(s[j][0], s[j][1]);
            *(float2*)&Pw[(g + 8) * KST + j * 8 + t * 2] =
                make_float2(s[j][2], s[j][3]);
        }
        __syncwarp();

        // ---- O += P @ V ----
        #pragma unroll
        for (int c = 0; c < 8; c++) {
            uint32_t ph[4], pl[4];
            tf32_split(Pw[g * KST + c * 8 + t],           ph[0], pl[0]);
            tf32_split(Pw[(g + 8) * KST + c * 8 + t],     ph[1], pl[1]);
            tf32_split(Pw[g * KST + c * 8 + t + 4],       ph[2], pl[2]);
            tf32_split(Pw[(g + 8) * KST + c * 8 + t + 4], ph[3], pl[3]);
            #pragma unroll
            for (int j = 0; j < 8; j++) {
                // B frag: b0 = V[k=c*8+t][n=j*8+g]
                uint32_t bh[2], bl[2];
                tf32_split(Vs[(c * 8 + t) * KST + j * 8 + g],     bh[0], bl[0]);
                tf32_split(Vs[(c * 8 + t + 4) * KST + j * 8 + g], bh[1], bl[1]);
                mma8(o[j], ph, bh);
                mma8(o[j], pl, bh);
                mma8(o[j], ph, bl);
            }
        }
    }

    // ---- epilogue ----
    float inv0 = 1.f / lrow[0], inv1 = 1.f / lrow[1];
    #pragma unroll
    for (int j = 0; j < 8; j++) {
        float* Or0 = O + (size_t)(m0 + w * 16 + g) * AED + h * HD + j * 8 + t * 2;
        float* Or1 = Or0 + 8 * AED;
        *(float2*)Or0 = make_float2(o[j][0] * inv0, o[j][1] * inv0);
        *(float2*)Or1 = make_float2(o[j][2] * inv1, o[j][3] * inv1);
    }
}

// ================= persistent DKM (7579us-verified, untouched) =================
#define NB_DKM 128
#define XST  516
#define XST4 129
#define AS_ST 36
#define DKM_SMEM_FLOATS (2 * KCL * XST + KCL * AS_ST + 64)

__device__ __forceinline__ void grid_bar() {
    __syncthreads();
    if (threadIdx.x == 0) {
        __threadfence();
        unsigned gen = g_bar_gen;
        if (atomicAdd((unsigned*)&g_bar_arrive, 1u) == NB_DKM - 1) {
            g_bar_arrive = 0;
            __threadfence();
            g_bar_gen = gen + 1;
        } else {
            while (g_bar_gen == gen) { }
        }
        __threadfence();
    }
    __syncthreads();
}

__global__ void __launch_bounds__(256)
dkm_persist(const float* __restrict__ X, const int* __restrict__ idx,
            float* __restrict__ a_out) {
    extern __shared__ float sm[];
    float* Xs     = sm;
    float* Cs     = Xs + KCL * XST;
    float* a_s    = Cs + KCL * XST;
    float* asum_s = a_s + KCL * AS_ST;
    float* cn_s   = asum_s + KCL;
    __shared__ float redw[8];

    const int tid = threadIdx.x;
    const int b = blockIdx.x;
    const int tx = tid & 15, ty = tid >> 4;
    const int rbase = b * 32;
    const int w = tid >> 5, lane = tid & 31;

    for (int itr = 0; itr < 4; itr++) {
        int row = rbase + w * 4 + itr;
        const float4* xr = (const float4*)(X + (size_t)row * AED);
        float p = 0.f;
        #pragma unroll
        for (int i = 0; i < 4; i++) {
            float4 v = xr[i * 32 + lane];
            p += v.x*v.x + v.y*v.y + v.z*v.z + v.w*v.w;
        }
        #pragma unroll
        for (int off = 16; off >= 1; off >>= 1)
            p += __shfl_xor_sync(0xffffffffu, p, off);
        if (lane == 0) g_xn[row] = p;
    }
    for (int i = tid; i < KCL * 128; i += 256) {
        int r = i >> 7, c4 = i & 127;
        ((float4*)Xs)[r * XST4 + c4] =
            ((const float4*)X)[(size_t)(rbase + r) * 128 + c4];
    }
    if (tid < 128) g_Cacc[b * 128 + tid] = 0.f;
    if (b == 0) {
        for (int i = tid; i < KCL * AED; i += 256) {
            int r = i >> 9, c = i & 511;
            g_C[i] = X[(size_t)idx[r] * AED + c];
        }
        if (tid < KCL) g_asum[tid] = 0.f;
    }
    grid_bar();

    for (int it = 0; ; it++) {
        for (int i = tid; i < KCL * 128; i += 256) {
            int r = i >> 7, c4 = i & 127;
            ((float4*)Cs)[r * XST4 + c4] = ((const float4*)g_C)[r * 128 + c4];
        }
        if (tid < KCL) asum_s[tid] = 0.f;
        if (b == 0 && tid == 0) g_diff = 0.f;
        __syncthreads();
        {
            int j = tid >> 3, s7 = tid & 7;
            float p = 0.f;
            const float4* cr = (const float4*)(Cs + (size_t)j * XST);
            #pragma unroll
            for (int i = 0; i < 16; i++) {
                float4 v = cr[s7 * 16 + i];
                p += v.x*v.x + v.y*v.y + v.z*v.z + v.w*v.w;
            }
            p += __shfl_xor_sync(0xffffffffu, p, 4);
            p += __shfl_xor_sync(0xffffffffu, p, 2);
            p += __shfl_xor_sync(0xffffffffu, p, 1);
            if (s7 == 0) cn_s[j] = p;
        }
        __syncthreads();

        const ulonglong2* X0 = (const ulonglong2*)(Xs + (size_t)(ty * 2 + 0) * XST);
        const ulonglong2* X1 = (const ulonglong2*)(Xs + (size_t)(ty * 2 + 1) * XST);
        const ulonglong2* C0 = (const ulonglong2*)(Cs + (size_t)(tx * 2 + 0) * XST);
        const ulonglong2* C1 = (const ulonglong2*)(Cs + (size_t)(tx * 2 + 1) * XST);
        u64 dd[2][2];
        dd[0][0] = dd[0][1] = dd[1][0] = dd[1][1] = 0ull;
        #pragma unroll 4
        for (int k4 = 0; k4 < 128; k4++) {
            ulonglong2 a0 = X0[k4];
            ulonglong2 a1 = X1[k4];
            ulonglong2 b0 = C0[k4];
            ulonglong2 b1 = C1[k4];
            dd[0][0] = fma2(a0.x, b0.x, dd[0][0]);
            dd[0][0] = fma2(a0.y, b0.y, dd[0][0]);
            dd[0][1] = fma2(a0.x, b1.x, dd[0][1]);
            dd[0][1] = fma2(a0.y, b1.y, dd[0][1]);
            dd[1][0] = fma2(a1.x, b0.x, dd[1][0]);
            dd[1][0] = fma2(a1.y, b0.y, dd[1][0]);
            dd[1][1] = fma2(a1.x, b1.x, dd[1][1]);
            dd[1][1] = fma2(a1.y, b1.y, dd[1][1]);
        }
        float dot[2][2];
        #pragma unroll
        for (int i = 0; i < 2; i++)
            #pragma unroll
            for (int j = 0; j < 2; j++) {
                float2 t2 = upk2(dd[i][j]);
                dot[i][j] = t2.x + t2.y;
            }

        float asum_part[2] = {0.f, 0.f};
        #pragma unroll
        for (int i = 0; i < 2; i++) {
            int row = rbase + ty * 2 + i;
            float xn = g_xn[row];
            float lg[2];
            #pragma unroll
            for (int j = 0; j < 2; j++) {
                float d2 = xn + cn_s[tx * 2 + j] - 2.f * dot[i][j];
                lg[j] = -2.f * sqrtf(fmaxf(d2, 0.f));
            }
            float mx = fmaxf(lg[0], lg[1]);
            #pragma unroll
            for (int off = 8; off >= 1; off >>= 1)
                mx = fmaxf(mx, __shfl_xor_sync(0xffffffffu, mx, off));
            float e0 = __expf(lg[0] - mx), e1 = __expf(lg[1] - mx);
            float ss = e0 + e1;
            #pragma unroll
            for (int off = 8; off >= 1; off >>= 1)
                ss += __shfl_xor_sync(0xffffffffu, ss, off);
            float inv = 1.f / ss;
            float a0v = e0 * inv, a1v = e1 * inv;
            a_out[(size_t)row * KCL + tx * 2 + 0] = a0v;
            a_out[(size_t)row * KCL + tx * 2 + 1] = a1v;
            a_s[(ty * 2 + i) * AS_ST + tx * 2 + 0] = a0v;
            a_s[(ty * 2 + i) * AS_ST + tx * 2 + 1] = a1v;
            asum_part[0] += a0v; asum_part[1] += a1v;
        }
        atomicAdd(&asum_s[tx * 2 + 0], asum_part[0]);
        atomicAdd(&asum_s[tx * 2 + 1], asum_part[1]);
        __syncthreads();
        if (tid < KCL) atomicAdd(&g_asum[tid], asum_s[tid]);

        {
            const int k4 = tid & 127;
            const int jg = tid >> 7;
            u64 av2[16][2];
            #pragma unroll
            for (int jj = 0; jj < 16; jj++) { av2[jj][0] = 0ull; av2[jj][1] = 0ull; }
            for (int r = 0; r < 32; r++) {
                ulonglong2 x2 = *(const ulonglong2*)(Xs + (size_t)r * XST + k4 * 4);
                #pragma unroll
                for (int q = 0; q < 4; q++) {
                    float4 av = ((const float4*)a_s)[r * 9 + jg * 4 + q];
                    float a[4] = {av.x, av.y, av.z, av.w};
                    #pragma unroll
                    for (int u = 0; u < 4; u++) {
                        int jj = q * 4 + u;
                        u64 pu = pk2(a[u], a[u]);
                        av2[jj][0] = fma2(pu, x2.x, av2[jj][0]);
                        av2[jj][1] = fma2(pu, x2.y, av2[jj][1]);
                    }
                }
            }
            #pragma unroll
            for (int jj = 0; jj < 16; jj++) {
                float* dst = g_Cacc + (size_t)(jg * 16 + jj) * AED + k4 * 4;
                float2 lo = upk2(av2[jj][0]);
                float2 hi = upk2(av2[jj][1]);
                atomicAdd(dst + 0, lo.x);
                atomicAdd(dst + 1, lo.y);
                atomicAdd(dst + 2, hi.x);
                atomicAdd(dst + 3, hi.y);
            }
        }
        grid_bar();

        float dsum = 0.f;
        if (tid < 128) {
            int i = b * 128 + tid;
            int j = i >> 9;
            float cn_ = g_Cacc[i] / (g_asum[j] + EPSK);
            g_Cnew[i] = cn_;
            dsum = fabsf(cn_ - g_C[i]);
        }
        #pragma unroll
        for (int off = 16; off >= 1; off >>= 1)
            dsum += __shfl_xor_sync(0xffffffffu, dsum, off);
        if (lane == 0) redw[w] = dsum;
        __syncthreads();
        if (tid == 0) {
            float t2 = redw[0] + redw[1] + redw[2] + redw[3]
                     + redw[4] + redw[5] + redw[6] + redw[7];
            atomicAdd(&g_diff, t2);
        }
        grid_bar();

        float diff = *((volatile float*)&g_diff);
        if (it == MAX_IT || !(diff > THRS)) break;
        if (tid < 128) {
            int i = b * 128 + tid;
            g_C[i] = g_Cnew[i];
            g_Cacc[i] = 0.f;
        }
        if (b == 0 && tid < KCL) g_asum[tid] = 0.f;
        grid_bar();
    }
}

__global__ void copy_out(float* __restrict__ out) {
    int i = blockIdx.x * 256 + threadIdx.x;
    out[i] = g_C[i];
}

// ================= launch =================
extern "C" void kernel_launch(void* const* d_in, const int* in_sizes, int n_in,
                              void* d_out, int out_size) {
    const float* X   = (const float*)d_in[0];
    const float* qw  = (const float*)d_in[1];
    const float* kw  = (const float*)d_in[2];
    const float* vw  = (const float*)d_in[3];
    const float* ipw = (const float*)d_in[4];
    const float* ipb = (const float*)d_in[5];
    const float* ow  = (const float*)d_in[6];
    const float* ob  = (const float*)d_in[7];
    const int*   idx = (const int*)d_in[8];

    float* out   = (float*)d_out;
    float* a_out = out + KCL * AED;

    cudaFuncSetAttribute(attn_mma, cudaFuncAttributeMaxDynamicSharedMemorySize,
                         ATTN_SMEM_FLOATS * 4);
    cudaFuncSetAttribute(dkm_persist, cudaFuncAttributeMaxDynamicSharedMemorySize,
                         DKM_SMEM_FLOATS * 4);

    // fused projection weights: W*F = qw @ Wq^T etc.  [768,512]
    dim3 gW(AED/64, EMB/64);
    gemm64<true, false><<<gW, 256>>>(qw, ipw,               nullptr, g_WqF, EMB, AED, AED);
    gemm64<true, false><<<gW, 256>>>(kw, ipw + AED*AED,     nullptr, g_WkF, EMB, AED, AED);
    gemm64<true, false><<<gW, 256>>>(vw, ipw + 2*AED*AED,   nullptr, g_WvF, EMB, AED, AED);

    // projections [4096,512] = X @ WF + b
    dim3 gP(AED/64, N_TOK/64);
    gemm64<false, true><<<gP, 256>>>(X, g_WqF, ipb,          g_QH, N_TOK, AED, EMB);
    gemm64<false, true><<<gP, 256>>>(X, g_WkF, ipb + AED,    g_KH, N_TOK, AED, EMB);
    gemm64<false, true><<<gP, 256>>>(X, g_WvF, ipb + 2*AED,  g_VH, N_TOK, AED, EMB);

    // attention (tf32 mma, fp32-accurate via 3-term split)
    attn_mma<<<dim3(N_TOK/64, NH), 128, ATTN_SMEM_FLOATS*4>>>(g_QH, g_KH, g_VH, g_AO);

    // output projection
    gemm64<true, true><<<gP, 256>>>(g_AO, ow, ob, g_TR, N_TOK, AED, AED);

    // persistent DKM
    dkm_persist<<<NB_DKM, 256, DKM_SMEM_FLOATS*4>>>(g_TR, idx, a_out);

    copy_out<<<KCL*AED/256, 256>>>(out);
}